// round 15
// baseline (speedup 1.0000x reference)
#include <cuda_runtime.h>
#include <cuda_fp16.h>
#include <math.h>
#include <stdint.h>

#define N_NODES 8192
#define IN_F    256
#define OUT_F   64
#define QSPLIT  4
#define KQ      (N_NODES / QSPLIT)     // 2048 j per CTA
#define CH      32                     // j per chunk (2 ksteps of 16)
#define NCH     (KQ / CH)              // 64 chunks
#define MT      128                    // rows per CTA (4 warps x 32)
#define TPB     128
#define PS      132
#define BSLOTS  576                    // B: 2 ksteps * 9 nblk * 32 lanes (float4)
#define BBYTES  (BSLOTS * 16)          // 9216 B
#define ADJB    (MT * CH * 4)          // 16384 B adj chunk
#define STGB    (BBYTES + ADJB)        // 25600 B per ring stage
#define NSTG    2                      // cp.async ring stages
#define SMEM_K2 (NSTG * STGB + 512)    // 51712 B dynamic smem
#define HESCALE 0.03125f               // 2^-5: keeps he inside fp16 range
#define HEINV   32.0f

// ---------------- static device scratch ------------------------------------
__device__ float  g_f1[N_NODES], g_E1[N_NODES], g_Q1[N_NODES], g_f2v[N_NODES];
// fp16 fragment-ordered B: [jstep16][nblk8+den][lane][8 halves]
__device__ __half g_Bh[N_NODES / 16][9][32][8];           // 2.36 MB (L2-resident)
__device__ float  g_pD[QSPLIT][N_NODES][PS];              // partials

// ---------------- helpers ----------------------------------------------------
__device__ __forceinline__ uint32_t smem_u32(const void* p) {
    uint32_t a;
    asm("{ .reg .u64 t; cvta.to.shared.u64 t, %1; cvt.u32.u64 %0, t; }"
        : "=r"(a) : "l"(p));
    return a;
}
// two mask bits (sh, sh+1) -> packed half2 {0|1, 0|1}
__device__ __forceinline__ uint32_t bit2h(unsigned w, int sh) {
    unsigned b = w >> sh;
    return ((b & 1u) ? 0x3C00u : 0u) | ((b & 2u) ? 0x3C000000u : 0u);
}
__device__ __forceinline__ void mma16(float* d, uint32_t a0, uint32_t a1,
                                      uint32_t a2, uint32_t a3,
                                      uint32_t b0, uint32_t b1) {
    asm volatile(
        "mma.sync.aligned.m16n8k16.row.col.f32.f16.f16.f32 "
        "{%0,%1,%2,%3}, {%4,%5,%6,%7}, {%8,%9}, {%0,%1,%2,%3};"
        : "+f"(d[0]), "+f"(d[1]), "+f"(d[2]), "+f"(d[3])
        : "r"(a0), "r"(a1), "r"(a2), "r"(a3), "r"(b0), "r"(b1));
}
#define CP16(sdst, gsrc) \
    asm volatile("cp.async.cg.shared.global [%0], [%1], 16;" \
                 :: "r"(sdst), "l"(gsrc) : "memory")
#define CP_COMMIT() asm volatile("cp.async.commit_group;" ::: "memory")
#define CP_WAIT1()  asm volatile("cp.async.wait_group 1;" ::: "memory")

// ---------------- kernel 1: h = X@W, scalars + fp16 B-pack (R13 form) ------
__global__ void __launch_bounds__(TPB)
k_h(const float* __restrict__ X, const float* __restrict__ W,
    const float* __restrict__ a) {
    __shared__ float4 sx[16 * (IN_F / 4)];       // 16 rows x 1KB = 16KB

    int t = threadIdx.x, warp = t >> 5, lane = t & 31;
    int rbase = blockIdx.x * 16;

    const float4* xsrc = (const float4*)(X + (size_t)rbase * IN_F);
    #pragma unroll
    for (int i = 0; i < 1024 / TPB; i++)
        sx[i * TPB + t] = xsrc[i * TPB + t];
    __syncthreads();

    int c0 = 2 * lane;
    float2 acc[4];
    #pragma unroll
    for (int r = 0; r < 4; r++) acc[r] = make_float2(0.f, 0.f);

    const float4* sxw = sx + (warp * 4) * (IN_F / 4);
    #pragma unroll 4
    for (int kg = 0; kg < IN_F / 4; kg++) {
        float4 xv[4];
        #pragma unroll
        for (int r = 0; r < 4; r++)
            xv[r] = sxw[r * (IN_F / 4) + kg];
        #pragma unroll
        for (int kk = 0; kk < 4; kk++) {
            float2 w2 = __ldg((const float2*)(W + (kg * 4 + kk) * OUT_F + c0));
            const float* xp;
            #pragma unroll
            for (int r = 0; r < 4; r++) {
                xp = (const float*)&xv[r];
                acc[r].x = fmaf(xp[kk], w2.x, acc[r].x);
                acc[r].y = fmaf(xp[kk], w2.y, acc[r].y);
            }
        }
    }

    float a1x = __ldg(a + c0),      a1y = __ldg(a + c0 + 1);
    float a2x = __ldg(a + 64 + c0), a2y = __ldg(a + 64 + c0 + 1);

    float e2a[4], q2a[4], p1a[4], p2a[4];
    #pragma unroll
    for (int r = 0; r < 4; r++) {
        float p1 = acc[r].x * a1x + acc[r].y * a1y;
        float p2 = acc[r].x * a2x + acc[r].y * a2y;
        #pragma unroll
        for (int o = 16; o > 0; o >>= 1) {
            p1 += __shfl_xor_sync(0xffffffffu, p1, o);
            p2 += __shfl_xor_sync(0xffffffffu, p2, o);
        }
        p1a[r] = p1; p2a[r] = p2;
        e2a[r] = expf(p2); q2a[r] = expf(0.2f * p2);
    }

    #pragma unroll
    for (int pr = 0; pr < 2; pr++) {
        int ra = rbase + warp * 4 + 2 * pr;
        int s16 = ra >> 4;
        int reg = (ra >> 3) & 1, cc = (ra & 7) >> 1;
        float heA0 = acc[2*pr].x     * e2a[2*pr]     * HESCALE;
        float heB0 = acc[2*pr + 1].x * e2a[2*pr + 1] * HESCALE;
        float hqA0 = acc[2*pr].x     * q2a[2*pr];
        float hqB0 = acc[2*pr + 1].x * q2a[2*pr + 1];
        float heA1 = acc[2*pr].y     * e2a[2*pr]     * HESCALE;
        float heB1 = acc[2*pr + 1].y * e2a[2*pr + 1] * HESCALE;
        float hqA1 = acc[2*pr].y     * q2a[2*pr];
        float hqB1 = acc[2*pr + 1].y * q2a[2*pr + 1];
        {
            __half* cell = g_Bh[s16][c0 >> 3][((c0 & 7) << 2) | cc];
            *(__half2*)&cell[2 * reg]     = __floats2half2_rn(heA0, heB0);
            *(__half2*)&cell[4 + 2 * reg] = __floats2half2_rn(hqA0, hqB0);
        }
        {
            int d = c0 + 1;
            __half* cell = g_Bh[s16][d >> 3][((d & 7) << 2) | cc];
            *(__half2*)&cell[2 * reg]     = __floats2half2_rn(heA1, heB1);
            *(__half2*)&cell[4 + 2 * reg] = __floats2half2_rn(hqA1, hqB1);
        }
        if (lane == 0) {
            __half* bd = g_Bh[s16][8][cc];
            *(__half2*)&bd[2 * reg] =
                __floats2half2_rn(e2a[2*pr] * HESCALE, e2a[2*pr + 1] * HESCALE);
            *(__half2*)&bd[4 + 2 * reg] =
                __floats2half2_rn(q2a[2*pr], q2a[2*pr + 1]);
            #pragma unroll
            for (int ii = 0; ii < 2; ii++) {
                int row = ra + ii;
                g_f1[row]  = p1a[2*pr + ii];
                g_E1[row]  = expf(p1a[2*pr + ii]);
                g_Q1[row]  = expf(0.2f * p1a[2*pr + ii]);
                g_f2v[row] = p2a[2*pr + ii];
            }
        }
    }
}

// ---------------- kernel 2: fp16 m16n8k16 GEMM, adj staged via cp.async -----
// Each ring stage = B chunk (9.2KB) + adj chunk (128x32 int, 16KB), both
// fetched by cp.async with deep MLP, overlapping the previous chunk's MMAs.
// Producer reads adj from SMEM (conflict-free 128B rows) -> ballots.
// 2-stage ring, distance 1 (per-chunk barrier bounds readers; writer
// (ch+1)&1 never collides with reader ch&1).
__global__ void __launch_bounds__(TPB, 2)
k_attn(const int* __restrict__ adj) {
    extern __shared__ char dsm[];
    float*  s_f1 = (float*)(dsm + NSTG * STGB);

    int t = threadIdx.x, lane = t & 31, wid = t >> 5;
    int g = lane >> 2, c = lane & 3;
    int strip = blockIdx.x * MT;
    int q = blockIdx.y, jq = q * KQ;

    uint32_t smb = smem_u32(dsm);
    const char* bsrc = (const char*)&g_Bh[jq >> 4][0][0][0];
    const int*  asrc = adj + (size_t)strip * N_NODES + jq;

    // prologue: prefetch chunk 0 (B + adj)
    {
        for (int i = t; i < BSLOTS; i += TPB)
            CP16(smb + i * 16, bsrc + (size_t)i * 16);
        #pragma unroll
        for (int i = 0; i < (MT * CH * 4 / 16) / TPB; i++) {   // 8 per thread
            int idx = i * TPB + t;                  // 0..1023
            int row = idx >> 3, seg = idx & 7;
            CP16(smb + BBYTES + row * 128 + seg * 16,
                 asrc + (size_t)row * N_NODES + seg * 4);
        }
        CP_COMMIT();
    }
    if (t < MT) s_f1[t] = g_f1[strip + t];
    __syncthreads();                                // s_f1 visible

    float aP[2][9][4], aN[2][9][4];
    #pragma unroll
    for (int m = 0; m < 2; m++)
        #pragma unroll
        for (int b = 0; b < 9; b++)
            #pragma unroll
            for (int v = 0; v < 4; v++) { aP[m][b][v] = 0.f; aN[m][b][v] = 0.f; }

    for (int ch = 0; ch < NCH; ch++) {
        int stg = ch & 1;

        // (a) prefetch chunk ch+1 into the other stage; ALWAYS commit
        if (ch + 1 < NCH) {
            uint32_t d0 = smb + ((ch + 1) & 1) * STGB;
            const char* b0 = bsrc + (size_t)(ch + 1) * BBYTES;
            for (int i = t; i < BSLOTS; i += TPB)
                CP16(d0 + i * 16, b0 + (size_t)i * 16);
            const int* a0 = asrc + (ch + 1) * CH;
            #pragma unroll
            for (int i = 0; i < (MT * CH * 4 / 16) / TPB; i++) {
                int idx = i * TPB + t;
                int row = idx >> 3, seg = idx & 7;
                CP16(d0 + BBYTES + row * 128 + seg * 16,
                     a0 + (size_t)row * N_NODES + seg * 4);
            }
        }
        CP_COMMIT();

        // (b) chunk ch resident + visible
        CP_WAIT1();
        __syncthreads();

        // (c) producer: adj from SMEM (batched LDS), sign ballots -> masks
        float f2l = g_f2v[jq + ch * CH + lane];
        const int* sadj = (const int*)(dsm + stg * STGB + BBYTES) + wid * 32 * CH;
        int av[32];
        #pragma unroll
        for (int rr = 0; rr < 32; rr++)             // independent LDS, pipelined
            av[rr] = sadj[rr * CH + lane];
        unsigned P[4] = {0,0,0,0}, Nn[4] = {0,0,0,0};
        #pragma unroll
        for (int rr = 0; rr < 32; rr++) {
            float f1r = s_f1[wid * 32 + rr];
            bool nz  = (av[rr] != 0);
            bool pos = (f1r + f2l) >= 0.f;
            unsigned Pm = __ballot_sync(0xffffffffu, nz && pos);
            unsigned Nm = __ballot_sync(0xffffffffu, nz && !pos);
            if ((rr & 7) == g) { P[rr >> 3] = Pm; Nn[rr >> 3] = Nm; }
        }

        // (d) MMA: 2 ksteps x 9 nblk x {P,N} x 2 mtiles = 72 m16n8k16
        const float4* bbs = (const float4*)(dsm + stg * STGB) + lane;
        #pragma unroll
        for (int s = 0; s < 2; s++) {
            int sh = (s << 4) + (c << 1);
            uint32_t pa[2][4], na[2][4];
            #pragma unroll
            for (int m = 0; m < 2; m++) {
                pa[m][0] = bit2h(P[2*m],   sh);     pa[m][1] = bit2h(P[2*m+1], sh);
                pa[m][2] = bit2h(P[2*m],   sh + 8); pa[m][3] = bit2h(P[2*m+1], sh + 8);
                na[m][0] = bit2h(Nn[2*m],  sh);     na[m][1] = bit2h(Nn[2*m+1], sh);
                na[m][2] = bit2h(Nn[2*m],  sh + 8); na[m][3] = bit2h(Nn[2*m+1], sh + 8);
            }
            const float4* bp = bbs + s * 9 * 32;
            #pragma unroll
            for (int b = 0; b < 9; b++) {
                float4 f = bp[b * 32];
                uint32_t be0 = __float_as_uint(f.x), be1 = __float_as_uint(f.y);
                uint32_t bq0 = __float_as_uint(f.z), bq1 = __float_as_uint(f.w);
                if (b == 8 && g != 0) { be0 = be1 = bq0 = bq1 = 0u; }
                #pragma unroll
                for (int m = 0; m < 2; m++) {
                    mma16(aP[m][b], pa[m][0], pa[m][1], pa[m][2], pa[m][3], be0, be1);
                    mma16(aN[m][b], na[m][0], na[m][1], na[m][2], na[m][3], bq0, bq1);
                }
            }
        }
        __syncthreads();   // done reading stage stg before it is re-filled
    }

    // ---- epilogue: store fragments to partials ----
    #pragma unroll
    for (int m = 0; m < 2; m++) {
        int r0 = strip + wid * 32 + 16 * m + g, r1 = r0 + 8;
        float* p0 = &g_pD[q][r0][0];
        float* p1 = &g_pD[q][r1][0];
        #pragma unroll
        for (int b = 0; b < 8; b++) {
            int col = 8 * b + 2 * c;
            *(float2*)(p0 + col)      = make_float2(aP[m][b][0], aP[m][b][1]);
            *(float2*)(p1 + col)      = make_float2(aP[m][b][2], aP[m][b][3]);
            *(float2*)(p0 + 64 + col) = make_float2(aN[m][b][0], aN[m][b][1]);
            *(float2*)(p1 + 64 + col) = make_float2(aN[m][b][2], aN[m][b][3]);
        }
        if (c == 0) {
            p0[128] = aP[m][8][0];  p0[129] = aN[m][8][0];
            p1[128] = aP[m][8][2];  p1[129] = aN[m][8][2];
        }
    }
}

// ---------------- kernel 3: combine splits, unscale, divide, ELU -----------
__global__ void k_final(float* __restrict__ out) {
    int row = blockIdx.x;
    int d = threadIdx.x;                 // 64 threads
    float e1 = g_E1[row], q1 = g_Q1[row];
    float n1 = 0.f, n2 = 0.f, de = 0.f, dq = 0.f;
    #pragma unroll
    for (int q = 0; q < QSPLIT; q++) {
        n1 += g_pD[q][row][d];
        n2 += g_pD[q][row][64 + d];
        de += g_pD[q][row][128];
        dq += g_pD[q][row][129];
    }
    n1 *= HEINV; de *= HEINV;            // undo exact 2^-5 he/E2 scaling
    float num = e1 * n1 + q1 * n2;
    float den = e1 * de + q1 * dq;
    float v = num / den;
    out[(size_t)row * OUT_F + d] = (v > 0.f) ? v : expm1f(v);
}

// ---------------- launch ----------------------------------------------------
extern "C" void kernel_launch(void* const* d_in, const int* in_sizes, int n_in,
                              void* d_out, int out_size) {
    const float* X = nullptr; const int* adj = nullptr;
    const float* W = nullptr; const float* a = nullptr;
    for (int i = 0; i < n_in; i++) {
        switch (in_sizes[i]) {
            case N_NODES * IN_F:    X   = (const float*)d_in[i]; break;
            case N_NODES * N_NODES: adj = (const int*)  d_in[i]; break;
            case IN_F * OUT_F:      W   = (const float*)d_in[i]; break;
            case 2 * OUT_F:         a   = (const float*)d_in[i]; break;
        }
    }
    cudaFuncSetAttribute(k_attn, cudaFuncAttributeMaxDynamicSharedMemorySize,
                         SMEM_K2);
    k_h<<<N_NODES / 16, TPB>>>(X, W, a);
    dim3 g2(N_NODES / MT, QSPLIT);
    k_attn<<<g2, TPB, SMEM_K2>>>(adj);
    k_final<<<N_NODES, OUT_F>>>((float*)d_out);
}

// round 16
// speedup vs baseline: 1.1538x; 1.1538x over previous
#include <cuda_runtime.h>
#include <cuda_fp16.h>
#include <math.h>
#include <stdint.h>

#define N_NODES 8192
#define IN_F    256
#define OUT_F   64
#define QSPLIT  4
#define KQ      (N_NODES / QSPLIT)     // 2048 j per CTA
#define CH      32                     // j per chunk (2 ksteps of 16)
#define NCH     (KQ / CH)              // 64 chunks
#define MT      128                    // rows per CTA (4 warps x 32)
#define TPB     128
#define PS      132
#define BSLOTS  576                    // 2 ksteps * 9 nblk * 32 lanes (float4)
#define BBYTES  (BSLOTS * 16)          // 9216 B per chunk stage
#define NSTG    4                      // cp.async ring stages
#define SMEM_K2 (NSTG * BBYTES + 512)  // 37376 B dynamic smem
#define HESCALE 0.03125f               // 2^-5: keeps he inside fp16 range
#define HEINV   32.0f

// ---------------- static device scratch ------------------------------------
__device__ float  g_f1[N_NODES], g_E1[N_NODES], g_Q1[N_NODES], g_f2v[N_NODES];
// fp16 fragment-ordered B: [jstep16][nblk8+den][lane][8 halves]
__device__ __half g_Bh[N_NODES / 16][9][32][8];           // 2.36 MB (L2-resident)
__device__ float  g_pD[QSPLIT][N_NODES][PS];              // partials

// ---------------- helpers ----------------------------------------------------
__device__ __forceinline__ uint32_t smem_u32(const void* p) {
    uint32_t a;
    asm("{ .reg .u64 t; cvta.to.shared.u64 t, %1; cvt.u32.u64 %0, t; }"
        : "=r"(a) : "l"(p));
    return a;
}
// two mask bits (sh, sh+1) -> packed half2 {0|1, 0|1}
__device__ __forceinline__ uint32_t bit2h(unsigned w, int sh) {
    unsigned b = w >> sh;
    return ((b & 1u) ? 0x3C00u : 0u) | ((b & 2u) ? 0x3C000000u : 0u);
}
__device__ __forceinline__ void mma16(float* d, uint32_t a0, uint32_t a1,
                                      uint32_t a2, uint32_t a3,
                                      uint32_t b0, uint32_t b1) {
    asm volatile(
        "mma.sync.aligned.m16n8k16.row.col.f32.f16.f16.f32 "
        "{%0,%1,%2,%3}, {%4,%5,%6,%7}, {%8,%9}, {%0,%1,%2,%3};"
        : "+f"(d[0]), "+f"(d[1]), "+f"(d[2]), "+f"(d[3])
        : "r"(a0), "r"(a1), "r"(a2), "r"(a3), "r"(b0), "r"(b1));
}
#define CP16(sdst, gsrc) \
    asm volatile("cp.async.cg.shared.global [%0], [%1], 16;" \
                 :: "r"(sdst), "l"(gsrc) : "memory")
#define CP_COMMIT() asm volatile("cp.async.commit_group;" ::: "memory")
#define CP_WAIT2()  asm volatile("cp.async.wait_group 2;" ::: "memory")

// ---------------- kernel 1: h = X@W, 8 rows/warp, fp16 B-pack --------------
// 32 rows per 128-thread CTA (grid 256): W L2 traffic halves vs 16-row CTAs
// and each W float2 LDG feeds 16 FFMAs (16 independent chains -> fma-pipe
// bound, not latency bound). Per-row accumulation order identical to R13.
__global__ void __launch_bounds__(TPB)
k_h(const float* __restrict__ X, const float* __restrict__ W,
    const float* __restrict__ a) {
    __shared__ float4 sx[32 * (IN_F / 4)];       // 32 rows x 1KB = 32KB

    int t = threadIdx.x, warp = t >> 5, lane = t & 31;
    int rbase = blockIdx.x * 32;

    // cooperative X stage: 32 rows x 64 float4 = 2048 float4, coalesced
    const float4* xsrc = (const float4*)(X + (size_t)rbase * IN_F);
    #pragma unroll
    for (int i = 0; i < 2048 / TPB; i++)
        sx[i * TPB + t] = xsrc[i * TPB + t];
    __syncthreads();

    int c0 = 2 * lane;                           // owned columns c0, c0+1
    float2 acc[8];
    #pragma unroll
    for (int r = 0; r < 8; r++) acc[r] = make_float2(0.f, 0.f);

    const float4* sxw = sx + (warp * 8) * (IN_F / 4);
    #pragma unroll 2
    for (int kg = 0; kg < IN_F / 4; kg++) {
        float4 xv[8];
        #pragma unroll
        for (int r = 0; r < 8; r++)
            xv[r] = sxw[r * (IN_F / 4) + kg];    // LDS.128 broadcast
        #pragma unroll
        for (int kk = 0; kk < 4; kk++) {
            float2 w2 = __ldg((const float2*)(W + (kg * 4 + kk) * OUT_F + c0));
            #pragma unroll
            for (int r = 0; r < 8; r++) {
                const float* xp = (const float*)&xv[r];
                acc[r].x = fmaf(xp[kk], w2.x, acc[r].x);
                acc[r].y = fmaf(xp[kk], w2.y, acc[r].y);
            }
        }
    }

    float a1x = __ldg(a + c0),      a1y = __ldg(a + c0 + 1);
    float a2x = __ldg(a + 64 + c0), a2y = __ldg(a + 64 + c0 + 1);

    float e2a[8], q2a[8], p1a[8], p2a[8];
    #pragma unroll
    for (int r = 0; r < 8; r++) {
        float p1 = acc[r].x * a1x + acc[r].y * a1y;
        float p2 = acc[r].x * a2x + acc[r].y * a2y;
        #pragma unroll
        for (int o = 16; o > 0; o >>= 1) {
            p1 += __shfl_xor_sync(0xffffffffu, p1, o);
            p2 += __shfl_xor_sync(0xffffffffu, p2, o);
        }
        p1a[r] = p1; p2a[r] = p2;
        e2a[r] = expf(p2); q2a[r] = expf(0.2f * p2);
    }

    // ---- fp16 B-pack: rows in (even, odd) pairs -> half2 stores ----
    #pragma unroll
    for (int pr = 0; pr < 4; pr++) {
        int ra = rbase + warp * 8 + 2 * pr;      // even row
        int s16 = ra >> 4;
        int reg = (ra >> 3) & 1, cc = (ra & 7) >> 1;
        float heA0 = acc[2*pr].x     * e2a[2*pr]     * HESCALE;
        float heB0 = acc[2*pr + 1].x * e2a[2*pr + 1] * HESCALE;
        float hqA0 = acc[2*pr].x     * q2a[2*pr];
        float hqB0 = acc[2*pr + 1].x * q2a[2*pr + 1];
        float heA1 = acc[2*pr].y     * e2a[2*pr]     * HESCALE;
        float heB1 = acc[2*pr + 1].y * e2a[2*pr + 1] * HESCALE;
        float hqA1 = acc[2*pr].y     * q2a[2*pr];
        float hqB1 = acc[2*pr + 1].y * q2a[2*pr + 1];
        {   // d = c0
            __half* cell = g_Bh[s16][c0 >> 3][((c0 & 7) << 2) | cc];
            *(__half2*)&cell[2 * reg]     = __floats2half2_rn(heA0, heB0);
            *(__half2*)&cell[4 + 2 * reg] = __floats2half2_rn(hqA0, hqB0);
        }
        {   // d = c0 + 1
            int d = c0 + 1;
            __half* cell = g_Bh[s16][d >> 3][((d & 7) << 2) | cc];
            *(__half2*)&cell[2 * reg]     = __floats2half2_rn(heA1, heB1);
            *(__half2*)&cell[4 + 2 * reg] = __floats2half2_rn(hqA1, hqB1);
        }
        if (lane == 0) {   // den slot (nblk 8, column 0)
            __half* bd = g_Bh[s16][8][cc];
            *(__half2*)&bd[2 * reg] =
                __floats2half2_rn(e2a[2*pr] * HESCALE, e2a[2*pr + 1] * HESCALE);
            *(__half2*)&bd[4 + 2 * reg] =
                __floats2half2_rn(q2a[2*pr], q2a[2*pr + 1]);
            #pragma unroll
            for (int ii = 0; ii < 2; ii++) {
                int row = ra + ii;
                g_f1[row]  = p1a[2*pr + ii];
                g_E1[row]  = expf(p1a[2*pr + ii]);
                g_Q1[row]  = expf(0.2f * p1a[2*pr + ii]);
                g_f2v[row] = p2a[2*pr + ii];
            }
        }
    }
}

// ---------------- kernel 2: binary-mask fp16 m16n8k16 GEMM (R13, verbatim) --
__global__ void __launch_bounds__(TPB, 2)
k_attn(const int* __restrict__ adj) {
    extern __shared__ char dsm[];
    float4* smB = (float4*)dsm;                  // NSTG stages, contiguous
    float*  s_f1 = (float*)(dsm + NSTG * BBYTES);

    int t = threadIdx.x, lane = t & 31, wid = t >> 5;
    int g = lane >> 2, c = lane & 3;
    int strip = blockIdx.x * MT;
    int q = blockIdx.y, jq = q * KQ;

    uint32_t smb = smem_u32(dsm);
    const char* bsrc = (const char*)&g_Bh[jq >> 4][0][0][0];

    #pragma unroll
    for (int pc = 0; pc < 2; pc++) {
        uint32_t d0 = smb + pc * BBYTES;
        const char* s0 = bsrc + (size_t)pc * BBYTES;
        for (int i = t; i < BSLOTS; i += TPB)
            CP16(d0 + i * 16, s0 + (size_t)i * 16);
        CP_COMMIT();
    }
    if (t < MT) s_f1[t] = g_f1[strip + t];
    __syncthreads();

    float aP[2][9][4], aN[2][9][4];
    #pragma unroll
    for (int m = 0; m < 2; m++)
        #pragma unroll
        for (int b = 0; b < 9; b++)
            #pragma unroll
            for (int v = 0; v < 4; v++) { aP[m][b][v] = 0.f; aN[m][b][v] = 0.f; }

    const int* ap0 = adj + (size_t)(strip + wid * 32) * N_NODES + jq + lane;

    for (int ch = 0; ch < NCH; ch++) {
        int stg = ch & (NSTG - 1);

        if (ch + 2 < NCH) {
            uint32_t d0 = smb + ((ch + 2) & (NSTG - 1)) * BBYTES;
            const char* s0 = bsrc + (size_t)(ch + 2) * BBYTES;
            for (int i = t; i < BSLOTS; i += TPB)
                CP16(d0 + i * 16, s0 + (size_t)i * 16);
        }
        CP_COMMIT();

        float f2l = g_f2v[jq + ch * CH + lane];
        const int* ap = ap0 + ch * CH;
        unsigned P[4] = {0,0,0,0}, Nn[4] = {0,0,0,0};
        #pragma unroll
        for (int rr = 0; rr < 32; rr++) {
            int av = ap[(size_t)rr * N_NODES];
            float f1r = s_f1[wid * 32 + rr];
            bool nz  = (av != 0);
            bool pos = (f1r + f2l) >= 0.f;
            unsigned Pm = __ballot_sync(0xffffffffu, nz && pos);
            unsigned Nm = __ballot_sync(0xffffffffu, nz && !pos);
            if ((rr & 7) == g) { P[rr >> 3] = Pm; Nn[rr >> 3] = Nm; }
        }

        CP_WAIT2();
        __syncthreads();

        #pragma unroll
        for (int s = 0; s < 2; s++) {
            int sh = (s << 4) + (c << 1);
            uint32_t pa[2][4], na[2][4];
            #pragma unroll
            for (int m = 0; m < 2; m++) {
                pa[m][0] = bit2h(P[2*m],   sh);     pa[m][1] = bit2h(P[2*m+1], sh);
                pa[m][2] = bit2h(P[2*m],   sh + 8); pa[m][3] = bit2h(P[2*m+1], sh + 8);
                na[m][0] = bit2h(Nn[2*m],  sh);     na[m][1] = bit2h(Nn[2*m+1], sh);
                na[m][2] = bit2h(Nn[2*m],  sh + 8); na[m][3] = bit2h(Nn[2*m+1], sh + 8);
            }
            const float4* bp = smB + stg * BSLOTS + s * 9 * 32 + lane;
            #pragma unroll
            for (int b = 0; b < 9; b++) {
                float4 f = bp[b * 32];
                uint32_t be0 = __float_as_uint(f.x), be1 = __float_as_uint(f.y);
                uint32_t bq0 = __float_as_uint(f.z), bq1 = __float_as_uint(f.w);
                if (b == 8 && g != 0) { be0 = be1 = bq0 = bq1 = 0u; }
                #pragma unroll
                for (int m = 0; m < 2; m++) {
                    mma16(aP[m][b], pa[m][0], pa[m][1], pa[m][2], pa[m][3], be0, be1);
                    mma16(aN[m][b], na[m][0], na[m][1], na[m][2], na[m][3], bq0, bq1);
                }
            }
        }
        __syncthreads();
    }

    #pragma unroll
    for (int m = 0; m < 2; m++) {
        int r0 = strip + wid * 32 + 16 * m + g, r1 = r0 + 8;
        float* p0 = &g_pD[q][r0][0];
        float* p1 = &g_pD[q][r1][0];
        #pragma unroll
        for (int b = 0; b < 8; b++) {
            int col = 8 * b + 2 * c;
            *(float2*)(p0 + col)      = make_float2(aP[m][b][0], aP[m][b][1]);
            *(float2*)(p1 + col)      = make_float2(aP[m][b][2], aP[m][b][3]);
            *(float2*)(p0 + 64 + col) = make_float2(aN[m][b][0], aN[m][b][1]);
            *(float2*)(p1 + 64 + col) = make_float2(aN[m][b][2], aN[m][b][3]);
        }
        if (c == 0) {
            p0[128] = aP[m][8][0];  p0[129] = aN[m][8][0];
            p1[128] = aP[m][8][2];  p1[129] = aN[m][8][2];
        }
    }
}

// ---------------- kernel 3: combine splits, unscale, divide, ELU -----------
// 4 rows per 256-thread block (grid 2048): 32x fewer blocks than before.
__global__ void __launch_bounds__(256)
k_final(float* __restrict__ out) {
    int idx = blockIdx.x * 256 + threadIdx.x;
    int row = idx >> 6, d = idx & 63;
    float e1 = g_E1[row], q1 = g_Q1[row];
    float n1 = 0.f, n2 = 0.f, de = 0.f, dq = 0.f;
    #pragma unroll
    for (int q = 0; q < QSPLIT; q++) {
        n1 += g_pD[q][row][d];
        n2 += g_pD[q][row][64 + d];
        de += g_pD[q][row][128];
        dq += g_pD[q][row][129];
    }
    n1 *= HEINV; de *= HEINV;            // undo exact 2^-5 he/E2 scaling
    float num = e1 * n1 + q1 * n2;
    float den = e1 * de + q1 * dq;
    float v = num / den;
    out[(size_t)row * OUT_F + d] = (v > 0.f) ? v : expm1f(v);
}

// ---------------- launch ----------------------------------------------------
extern "C" void kernel_launch(void* const* d_in, const int* in_sizes, int n_in,
                              void* d_out, int out_size) {
    const float* X = nullptr; const int* adj = nullptr;
    const float* W = nullptr; const float* a = nullptr;
    for (int i = 0; i < n_in; i++) {
        switch (in_sizes[i]) {
            case N_NODES * IN_F:    X   = (const float*)d_in[i]; break;
            case N_NODES * N_NODES: adj = (const int*)  d_in[i]; break;
            case IN_F * OUT_F:      W   = (const float*)d_in[i]; break;
            case 2 * OUT_F:         a   = (const float*)d_in[i]; break;
        }
    }
    cudaFuncSetAttribute(k_attn, cudaFuncAttributeMaxDynamicSharedMemorySize,
                         SMEM_K2);
    k_h<<<N_NODES / 32, TPB>>>(X, W, a);
    dim3 g2(N_NODES / MT, QSPLIT);
    k_attn<<<g2, TPB, SMEM_K2>>>(adj);
    k_final<<<N_NODES * OUT_F / 256, 256>>>((float*)d_out);
}